// round 16
// baseline (speedup 1.0000x reference)
#include <cuda_runtime.h>

#define NUM_ENT 50000
#define NUM_REL 237
#define REXT    238
#define D       64
#define BN_EPS  1e-5f
#define MAXE    800000

#define NTB_ROWS 128                      // rows per block
#define NT_WPAD  68
#define NT_XPAD  132
#define NT_XK    8                        // k-chunk per X stage
#define NT_SMEM  ((192 * NT_WPAD + NT_XK * NT_XPAD) * 4)   // 56.4 KB -> 4 blocks/SM

// ---------------- device scratch ----------------
__device__ float g_SO[NUM_ENT * D];
__device__ float g_SI[NUM_ENT * D];
__device__ float g_nbuf[NUM_ENT * D];
__device__ float g_rext[REXT * D];
__device__ float g_sum[D], g_sumsq[D];
__device__ unsigned int g_barrier;
// CSR scratch (built once per launch; graph is layer-invariant)
__device__ int  g_cnt[NUM_ENT];
__device__ int  g_rowptr[NUM_ENT + 1];
__device__ int  g_cursor[NUM_ENT];
__device__ int2 g_meta[MAXE];            // {src | etype<<16 | mask<<24, norm bits}

// ---- f32x2 packed helpers ----
__device__ __forceinline__ void fma2(unsigned long long& d,
                                     unsigned long long a,
                                     unsigned long long b) {
    asm("fma.rn.f32x2 %0, %1, %2, %0;" : "+l"(d) : "l"(a), "l"(b));
}
__device__ __forceinline__ unsigned long long pack2(float lo, float hi) {
    unsigned long long p;
    asm("mov.b64 %0, {%1, %2};" : "=l"(p) : "f"(lo), "f"(hi));
    return p;
}
__device__ __forceinline__ void unpack2(unsigned long long p, float& lo, float& hi) {
    asm("mov.b64 {%0, %1}, %2;" : "=f"(lo), "=f"(hi) : "l"(p));
}

// ---------------- init (once): layer-0 r_ext + zero cnt/stats/barrier ----------------
__global__ void init_kernel(const float* __restrict__ r0,
                            const float* __restrict__ LR0) {
    int tid0 = blockIdx.x * blockDim.x + threadIdx.x;
    int stride = gridDim.x * blockDim.x;
    for (int i = tid0; i < NUM_ENT; i += stride) g_cnt[i] = 0;
    for (int i = tid0; i < REXT * D; i += stride)
        g_rext[i] = (i < NUM_REL * D) ? __ldg(r0 + i) : __ldg(LR0 + i - NUM_REL * D);
    if (tid0 < D) { g_sum[tid0] = 0.f; g_sumsq[tid0] = 0.f; }
    if (tid0 == 0) g_barrier = 0u;
}

// ---------------- CSR build: histogram ----------------
__global__ __launch_bounds__(256) void hist_kernel(const int* __restrict__ dst, int E) {
    int e0 = (blockIdx.x * blockDim.x + threadIdx.x) * 4;
    int d[4];
#pragma unroll
    for (int j = 0; j < 4; j++)
        if (e0 + j < E) d[j] = __ldg(dst + e0 + j);
#pragma unroll
    for (int j = 0; j < 4; j++)
        if (e0 + j < E) atomicAdd(&g_cnt[d[j]], 1);
}

// ---------------- CSR build: single-block scan -> row_ptr, cursor ----------------
__global__ __launch_bounds__(1024) void scan_kernel(int E) {
    __shared__ int ssum[1024];
    const int per = (NUM_ENT + 1023) / 1024;   // 49
    int t = threadIdx.x;
    int base = t * per;
    int cnt_loc[49];
    int s = 0;
#pragma unroll
    for (int i = 0; i < per; i++) {
        int idx = base + i;
        int c = (idx < NUM_ENT) ? g_cnt[idx] : 0;
        cnt_loc[i] = c;
        s += c;
    }
    ssum[t] = s;
    __syncthreads();
    for (int off = 1; off < 1024; off <<= 1) {
        int v = (t >= off) ? ssum[t - off] : 0;
        __syncthreads();
        ssum[t] += v;
        __syncthreads();
    }
    int run = ssum[t] - s;   // exclusive prefix
#pragma unroll
    for (int i = 0; i < per; i++) {
        int idx = base + i;
        if (idx < NUM_ENT) {
            g_rowptr[idx] = run;
            g_cursor[idx] = run;
            run += cnt_loc[i];
        }
    }
    if (t == 1023) g_rowptr[NUM_ENT] = E;
}

// ---------------- CSR build: scatter packed edge meta (4 edges/thread) ----------------
__global__ __launch_bounds__(256) void csr_scatter_kernel(
    const int* __restrict__ src, const int* __restrict__ dst,
    const int* __restrict__ etype, const int* __restrict__ mask,
    const float* __restrict__ norm, int E)
{
    int e0 = (blockIdx.x * blockDim.x + threadIdx.x) * 4;
    if (e0 >= E) return;
    int ecnt = E - e0; if (ecnt > 4) ecnt = 4;
    int d[4], packed[4]; float nm[4];
#pragma unroll
    for (int j = 0; j < 4; j++) {
        int e = (j < ecnt) ? (e0 + j) : e0;
        d[j] = __ldg(dst + e);
        packed[j] = __ldg(src + e) | (__ldg(etype + e) << 16) | (__ldg(mask + e) << 24);
        nm[j] = __ldg(norm + e);
    }
#pragma unroll
    for (int j = 0; j < 4; j++) {
        if (j < ecnt) {
            int pos = atomicAdd(&g_cursor[d[j]], 1);
            g_meta[pos] = make_int2(packed[j], __float_as_int(nm[j]));
        }
    }
}

// ---------------- gather-aggregate: warp per node, 4-edge unrolled (MLP 8) ----------------
// Writes full SO/SI rows (no zeroing needed anywhere).
__global__ __launch_bounds__(256) void gather_kernel(
    const float* __restrict__ nfeat_in0, int rows, int layer)
{
    if (blockIdx.x == 0 && threadIdx.x < D) {
        g_sum[threadIdx.x] = 0.f; g_sumsq[threadIdx.x] = 0.f;
        if (threadIdx.x == 0) g_barrier = 0u;
    }
    int w = (blockIdx.x * blockDim.x + threadIdx.x) >> 5;
    if (w >= rows) return;
    int lane = threadIdx.x & 31;
    const float* __restrict__ nf = layer ? g_nbuf : nfeat_in0;
    int c2 = lane * 2;

    int beg = __ldg(&g_rowptr[w]);
    int end = __ldg(&g_rowptr[w + 1]);

    float aOx = 0.f, aOy = 0.f, aIx = 0.f, aIy = 0.f;

    int i = beg;
    for (; i + 4 <= end; i += 4) {
        int2 mt[4];
#pragma unroll
        for (int j = 0; j < 4; j++) mt[j] = __ldg(&g_meta[i + j]);   // warp-uniform broadcasts
        float2 nv[4], rv[4];
#pragma unroll
        for (int j = 0; j < 4; j++) {
            int s = mt[j].x & 0xFFFF;
            nv[j] = __ldg(reinterpret_cast<const float2*>(nf + (size_t)s * D + c2));
        }
#pragma unroll
        for (int j = 0; j < 4; j++) {
            int t = (mt[j].x >> 16) & 0xFF;
            rv[j] = __ldg(reinterpret_cast<const float2*>(g_rext + t * D + c2));
        }
#pragma unroll
        for (int j = 0; j < 4; j++) {
            float nm = __int_as_float(mt[j].y);
            float cx = nv[j].x * rv[j].x * nm;
            float cy = nv[j].y * rv[j].y * nm;
            if (mt[j].x >> 24) { aOx += cx; aOy += cy; }
            else               { aIx += cx; aIy += cy; }
        }
    }
    for (; i < end; i++) {
        int2 mt = __ldg(&g_meta[i]);
        int   s  = mt.x & 0xFFFF;
        int   t  = (mt.x >> 16) & 0xFF;
        float nm = __int_as_float(mt.y);
        float2 nv = __ldg(reinterpret_cast<const float2*>(nf + (size_t)s * D + c2));
        float2 rv = __ldg(reinterpret_cast<const float2*>(g_rext + t * D + c2));
        float cx = nv.x * rv.x * nm;
        float cy = nv.y * rv.y * nm;
        if (mt.x >> 24) { aOx += cx; aOy += cy; }
        else            { aIx += cx; aIy += cy; }
    }

    float2 o; o.x = aOx; o.y = aOy;
    float2 q; q.x = aIx; q.y = aIy;
    *reinterpret_cast<float2*>(g_SO + (size_t)w * D + c2) = o;
    *reinterpret_cast<float2*>(g_SI + (size_t)w * D + c2) = q;
}

// ---------------- node transform + fused BN apply + tanh (grid spin barrier) ----------------
__global__ __launch_bounds__(256, 4) void node_transform(
    const float* __restrict__ nfeat_in0,
    const float* __restrict__ WS, const float* __restrict__ WO,
    const float* __restrict__ WI, const float* __restrict__ LR,
    const float* __restrict__ gamma, const float* __restrict__ beta,
    float* __restrict__ out_n,
    int rows, int layer)
{
    extern __shared__ float smem[];
    float* sW = smem;                    // [192][NT_WPAD]
    float* sX = smem + 192 * NT_WPAD;    // [NT_XK][NT_XPAD]

    const float* __restrict__ nf = layer ? g_nbuf : nfeat_in0;
    const int tid = threadIdx.x;
    const int tr  = tid >> 4;
    const int tc  = tid & 15;
    const int row0 = blockIdx.x * NTB_ROWS;
    const float third = 1.0f / 3.0f;

    const float* wsrc[3] = {WS, WO, WI};
#pragma unroll
    for (int s = 0; s < 3; s++) {
        for (int i4 = tid; i4 < 1024; i4 += 256) {
            int c  = i4 >> 4;
            int k4 = (i4 & 15) * 4;
            float4 w = __ldg(reinterpret_cast<const float4*>(wsrc[s] + c * D + k4));
            float m0 = third, m1 = third, m2 = third, m3 = third;
            if (s == 0) {
                m0 *= __ldg(LR + k4);     m1 *= __ldg(LR + k4 + 1);
                m2 *= __ldg(LR + k4 + 2); m3 *= __ldg(LR + k4 + 3);
            }
            int kb = s * 64 + k4;
            sW[(kb + 0) * NT_WPAD + c] = w.x * m0;
            sW[(kb + 1) * NT_WPAD + c] = w.y * m1;
            sW[(kb + 2) * NT_WPAD + c] = w.z * m2;
            sW[(kb + 3) * NT_WPAD + c] = w.w * m3;
        }
    }

    unsigned long long acc2[4][4];
#pragma unroll
    for (int rp = 0; rp < 4; rp++)
#pragma unroll
        for (int c = 0; c < 4; c++) acc2[rp][c] = 0ULL;

    const float* xsrc[3] = {nf, g_SO, g_SI};
    const int xoff = tr * 8;
    const int woff = tc * 4;

#pragma unroll
    for (int s = 0; s < 3; s++) {
#pragma unroll
        for (int ch = 0; ch < 8; ch++) {
            __syncthreads();
            {
                int row = tid >> 1;
                int k4  = (tid & 1) * 4;
                int grow = row0 + row;
                float4 v = make_float4(0.f, 0.f, 0.f, 0.f);
                if (grow < rows)
                    v = __ldg(reinterpret_cast<const float4*>(
                            xsrc[s] + (size_t)grow * D + ch * NT_XK + k4));
                sX[(k4 + 0) * NT_XPAD + row] = v.x;
                sX[(k4 + 1) * NT_XPAD + row] = v.y;
                sX[(k4 + 2) * NT_XPAD + row] = v.z;
                sX[(k4 + 3) * NT_XPAD + row] = v.w;
            }
            __syncthreads();

            const float* wseg = sW + (s * 64 + ch * NT_XK) * NT_WPAD + woff;
#pragma unroll
            for (int k = 0; k < NT_XK; k++) {
                ulonglong2 xa = *reinterpret_cast<const ulonglong2*>(sX + k * NT_XPAD + xoff);
                ulonglong2 xb = *reinterpret_cast<const ulonglong2*>(sX + k * NT_XPAD + xoff + 4);
                float4 wv = *reinterpret_cast<const float4*>(wseg + k * NT_WPAD);

                unsigned long long wd0 = pack2(wv.x, wv.x);
                unsigned long long wd1 = pack2(wv.y, wv.y);
                unsigned long long wd2 = pack2(wv.z, wv.z);
                unsigned long long wd3 = pack2(wv.w, wv.w);

                fma2(acc2[0][0], xa.x, wd0); fma2(acc2[0][1], xa.x, wd1);
                fma2(acc2[0][2], xa.x, wd2); fma2(acc2[0][3], xa.x, wd3);
                fma2(acc2[1][0], xa.y, wd0); fma2(acc2[1][1], xa.y, wd1);
                fma2(acc2[1][2], xa.y, wd2); fma2(acc2[1][3], xa.y, wd3);
                fma2(acc2[2][0], xb.x, wd0); fma2(acc2[2][1], xb.x, wd1);
                fma2(acc2[2][2], xb.x, wd2); fma2(acc2[2][3], xb.x, wd3);
                fma2(acc2[3][0], xb.y, wd0); fma2(acc2[3][1], xb.y, wd1);
                fma2(acc2[3][2], xb.y, wd2); fma2(acc2[3][3], xb.y, wd3);
            }
        }
    }

    // ---- per-thread BN partial stats (acc2 stays live) ----
    float s_[4] = {0.f, 0.f, 0.f, 0.f};
    float q_[4] = {0.f, 0.f, 0.f, 0.f};
#pragma unroll
    for (int rp = 0; rp < 4; rp++) {
        float lo[4], hi[4];
#pragma unroll
        for (int c = 0; c < 4; c++) unpack2(acc2[rp][c], lo[c], hi[c]);
        int r0g = row0 + tr * 8 + rp * 2;
        if (r0g < rows) {
#pragma unroll
            for (int c = 0; c < 4; c++) { s_[c] += lo[c]; q_[c] += lo[c] * lo[c]; }
        }
        if (r0g + 1 < rows) {
#pragma unroll
            for (int c = 0; c < 4; c++) { s_[c] += hi[c]; q_[c] += hi[c] * hi[c]; }
        }
    }

    // ---- block reduce stats into g_sum/g_sumsq ----
    __syncthreads();
    float* redS = sW;
    float* redQ = sW + 1024;
#pragma unroll
    for (int c = 0; c < 4; c++) {
        redS[(woff + c) * 16 + tr] = s_[c];
        redQ[(woff + c) * 16 + tr] = q_[c];
    }
    __syncthreads();
    if (tid < D) {
        float ss = 0.f, qq = 0.f;
#pragma unroll
        for (int t = 0; t < 16; t++) {
            ss += redS[tid * 16 + t];
            qq += redQ[tid * 16 + t];
        }
        atomicAdd(&g_sum[tid],   ss);
        atomicAdd(&g_sumsq[tid], qq);
    }
    __syncthreads();

    // ---- grid barrier: all blocks resident (391 <= 444) ----
    if (tid == 0) {
        __threadfence();
        atomicAdd(&g_barrier, 1u);
        while (atomicAdd(&g_barrier, 0u) < (unsigned)gridDim.x) { }
    }
    __syncthreads();

    // ---- compute BN scale/shift (fresh L2 reads) ----
    float* ssc = sW + 2048;
    float* ssh = sW + 2048 + D;
    if (tid < D) {
        float invN = 1.0f / (float)rows;
        float mean = __ldcg(&g_sum[tid]) * invN;
        float var  = fmaxf(__ldcg(&g_sumsq[tid]) * invN - mean * mean, 0.f);
        float rstd = rsqrtf(var + BN_EPS);
        float g = __ldg(gamma + tid);
        ssc[tid] = rstd * g;
        ssh[tid] = __ldg(beta + tid) - mean * rstd * g;
    }
    __syncthreads();

    // ---- apply BN + tanh to live accumulators, store directly ----
    float* dstp = layer ? out_n : g_nbuf;
    float4 sc = *reinterpret_cast<const float4*>(ssc + woff);
    float4 sh = *reinterpret_cast<const float4*>(ssh + woff);
#pragma unroll
    for (int rp = 0; rp < 4; rp++) {
        float lo[4], hi[4];
#pragma unroll
        for (int c = 0; c < 4; c++) unpack2(acc2[rp][c], lo[c], hi[c]);
        int r0g = row0 + tr * 8 + rp * 2;
        if (r0g < rows) {
            float4 y;
            y.x = tanhf(lo[0] * sc.x + sh.x);
            y.y = tanhf(lo[1] * sc.y + sh.y);
            y.z = tanhf(lo[2] * sc.z + sh.z);
            y.w = tanhf(lo[3] * sc.w + sh.w);
            *reinterpret_cast<float4*>(dstp + (size_t)r0g * D + woff) = y;
        }
        if (r0g + 1 < rows) {
            float4 y;
            y.x = tanhf(hi[0] * sc.x + sh.x);
            y.y = tanhf(hi[1] * sc.y + sh.y);
            y.z = tanhf(hi[2] * sc.z + sh.z);
            y.w = tanhf(hi[3] * sc.w + sh.w);
            *reinterpret_cast<float4*>(dstp + (size_t)(r0g + 1) * D + woff) = y;
        }
    }
}

// ---------------- finish: rel update only (smem-staged WR^T) ----------------
#define REL_BLOCKS (((NUM_REL + 1) * 32 + 255) / 256)
#define WRT_PAD 66
__global__ __launch_bounds__(256) void finish_kernel(
    const float* __restrict__ WR,
    float* __restrict__ out_r,
    const float* __restrict__ LR_next,
    int layer)
{
    __shared__ float sWRT[D * WRT_PAD];   // [k][j], padded
    for (int i4 = threadIdx.x; i4 < 1024; i4 += 256) {
        int j  = i4 >> 4;
        int k4 = (i4 & 15) * 4;
        float4 w = __ldg(reinterpret_cast<const float4*>(WR + j * D + k4));
        sWRT[(k4 + 0) * WRT_PAD + j] = w.x;
        sWRT[(k4 + 1) * WRT_PAD + j] = w.y;
        sWRT[(k4 + 2) * WRT_PAD + j] = w.z;
        sWRT[(k4 + 3) * WRT_PAD + j] = w.w;
    }
    __syncthreads();

    int g = blockIdx.x * 256 + threadIdx.x;
    int t = g >> 5;
    int lane = g & 31;
    int j0 = lane * 2;
    if (t < NUM_REL) {
        float* dst = layer ? out_r : g_rext;  // layer 0 rewrites r_ext in place
        float a0 = 0.f, a1 = 0.f;
#pragma unroll 8
        for (int k = 0; k < D; k++) {
            float v = __ldg(g_rext + t * D + k);           // warp broadcast
            float2 w2 = *reinterpret_cast<const float2*>(sWRT + k * WRT_PAD + j0);
            a0 += v * w2.x;
            a1 += v * w2.y;
        }
        __syncwarp();
        dst[t * D + j0]     = a0;
        dst[t * D + j0 + 1] = a1;
    } else if (t == NUM_REL && layer == 0) {
        g_rext[NUM_REL * D + j0]     = __ldg(LR_next + j0);
        g_rext[NUM_REL * D + j0 + 1] = __ldg(LR_next + j0 + 1);
    }
}

// ---------------- launch ----------------
extern "C" void kernel_launch(void* const* d_in, const int* in_sizes, int n_in,
                              void* d_out, int out_size) {
    const float* n0   = (const float*)d_in[0];
    const float* r0   = (const float*)d_in[1];
    const float* norm = (const float*)d_in[2];
    const int*   src  = (const int*)d_in[3];
    const int*   dst  = (const int*)d_in[4];
    const int*   et   = (const int*)d_in[5];
    const int*   msk  = (const int*)d_in[6];
    const int E    = in_sizes[3];
    const int rows = in_sizes[0] / D;

    float* out   = (float*)d_out;
    float* out_n = out;
    float* out_r = out + (size_t)NUM_ENT * D;

    cudaFuncSetAttribute(node_transform,
                         cudaFuncAttributeMaxDynamicSharedMemorySize, NT_SMEM);

    const int nt_blocks  = (rows + NTB_ROWS - 1) / NTB_ROWS;
    const int gth_blocks = (rows * 32 + 255) / 256;
    const int e4_blocks  = (E + 4 * 256 - 1) / (4 * 256);

    // ---- build CSR once (graph is layer-invariant) ----
    init_kernel<<<256, 256>>>(r0, (const float*)d_in[11]);   // LR_0
    hist_kernel<<<e4_blocks, 256>>>(dst, E);
    scan_kernel<<<1, 1024>>>(E);
    csr_scatter_kernel<<<e4_blocks, 256>>>(src, dst, et, msk, norm, E);

    for (int l = 0; l < 2; l++) {
        const float* WO = (const float*)d_in[7  + 7 * l];
        const float* WI = (const float*)d_in[8  + 7 * l];
        const float* WS = (const float*)d_in[9  + 7 * l];
        const float* WR = (const float*)d_in[10 + 7 * l];
        const float* LR = (const float*)d_in[11 + 7 * l];
        const float* GA = (const float*)d_in[12 + 7 * l];
        const float* BE = (const float*)d_in[13 + 7 * l];
        const float* LRn = (const float*)d_in[11 + 7 * 1];

        gather_kernel<<<gth_blocks, 256>>>(n0, rows, l);
        node_transform<<<nt_blocks, 256, NT_SMEM>>>(n0, WS, WO, WI, LR,
                                                    GA, BE, out_n, rows, l);
        finish_kernel<<<REL_BLOCKS, 256>>>(WR, out_r, LRn, l);
    }
}

// round 17
// speedup vs baseline: 1.3626x; 1.3626x over previous
#include <cuda_runtime.h>

#define NUM_ENT 50000
#define NUM_REL 237
#define REXT    238
#define D       64
#define BN_EPS  1e-5f

#define NTB_ROWS 128                      // rows per block
#define NT_WPAD  68
#define NT_XPAD  132
#define NT_XK    8                        // k-chunk per X stage
#define NT_SMEM  ((192 * NT_WPAD + NT_XK * NT_XPAD) * 4)   // 56.4 KB -> 4 blocks/SM
#define REL_BLOCKS (((NUM_REL + 1) * 32 + 255) / 256)      // 30

// ---------------- device scratch ----------------
__device__ float g_SO[NUM_ENT * D];
__device__ float g_SI[NUM_ENT * D];
__device__ float g_nbuf[NUM_ENT * D];
__device__ float g_rext[REXT * D];
__device__ float g_sum[D], g_sumsq[D];
__device__ unsigned int g_barrier;

// ---- f32x2 packed helpers ----
__device__ __forceinline__ void fma2(unsigned long long& d,
                                     unsigned long long a,
                                     unsigned long long b) {
    asm("fma.rn.f32x2 %0, %1, %2, %0;" : "+l"(d) : "l"(a), "l"(b));
}
__device__ __forceinline__ unsigned long long pack2(float lo, float hi) {
    unsigned long long p;
    asm("mov.b64 %0, {%1, %2};" : "=l"(p) : "f"(lo), "f"(hi));
    return p;
}
__device__ __forceinline__ void unpack2(unsigned long long p, float& lo, float& hi) {
    asm("mov.b64 {%0, %1}, %2;" : "=f"(lo), "=f"(hi) : "l"(p));
}

// ---------------- init (once): layer-0 r_ext + zero SO/SI + zero stats ----------------
__global__ void init_kernel(const float* __restrict__ r0,
                            const float* __restrict__ LR0) {
    int tid0 = blockIdx.x * blockDim.x + threadIdx.x;
    int stride = gridDim.x * blockDim.x;
    const int n4 = NUM_ENT * D / 4;
    float4 z = make_float4(0.f, 0.f, 0.f, 0.f);
    for (int i = tid0; i < n4; i += stride) {
        reinterpret_cast<float4*>(g_SO)[i] = z;
        reinterpret_cast<float4*>(g_SI)[i] = z;
    }
    for (int i = tid0; i < REXT * D; i += stride)
        g_rext[i] = (i < NUM_REL * D) ? __ldg(r0 + i) : __ldg(LR0 + i - NUM_REL * D);
    if (tid0 < D) { g_sum[tid0] = 0.f; g_sumsq[tid0] = 0.f; }
    if (tid0 == 0) g_barrier = 0u;
}

// ---------------- edge scatter: 4 edges per thread; block 0 zeroes BN stats + barrier ----------------
__global__ __launch_bounds__(256) void edge_scatter(
    const float* __restrict__ nfeat_in0,
    const int*   __restrict__ src,
    const int*   __restrict__ dst,
    const int*   __restrict__ etype,
    const int*   __restrict__ mask,
    const float* __restrict__ norm,
    int E, int layer)
{
    if (blockIdx.x == 0 && threadIdx.x < D) {
        g_sum[threadIdx.x] = 0.f; g_sumsq[threadIdx.x] = 0.f;
        if (threadIdx.x == 0) g_barrier = 0u;
    }
    const float* __restrict__ nf = layer ? g_nbuf : nfeat_in0;
    int gid = blockIdx.x * blockDim.x + threadIdx.x;
    int e0 = (gid >> 4) * 4;
    if (e0 >= E) return;
    int c = (gid & 15) * 4;

    int ecnt = E - e0; if (ecnt > 4) ecnt = 4;

    int   s[4], d[4], t[4], m[4];
    float nm[4];
#pragma unroll
    for (int i = 0; i < 4; i++) {
        int e = (i < ecnt) ? (e0 + i) : e0;
        s[i]  = __ldg(src + e);
        d[i]  = __ldg(dst + e);
        t[i]  = __ldg(etype + e);
        m[i]  = __ldg(mask + e);
        nm[i] = (i < ecnt) ? __ldg(norm + e) : 0.f;
    }

    float4 nv[4], rv[4];
#pragma unroll
    for (int i = 0; i < 4; i++)
        nv[i] = __ldg(reinterpret_cast<const float4*>(nf + (size_t)s[i] * D + c));
#pragma unroll
    for (int i = 0; i < 4; i++)
        rv[i] = __ldg(reinterpret_cast<const float4*>(g_rext + t[i] * D + c));

#pragma unroll
    for (int i = 0; i < 4; i++) {
        if (i < ecnt) {
            float4 cm;
            cm.x = nv[i].x * rv[i].x * nm[i];
            cm.y = nv[i].y * rv[i].y * nm[i];
            cm.z = nv[i].z * rv[i].z * nm[i];
            cm.w = nv[i].w * rv[i].w * nm[i];
            float* b = (m[i] ? g_SO : g_SI) + (size_t)d[i] * D + c;
            asm volatile("red.global.add.v4.f32 [%0], {%1,%2,%3,%4};"
                         :: "l"(b), "f"(cm.x), "f"(cm.y), "f"(cm.z), "f"(cm.w)
                         : "memory");
        }
    }
}

// ---------------- node transform + fused BN + tanh + rel-update + zeroing ----------------
// Blocks [0, ntb): GEMM tiles + BN + (layer 0) SO/SI zeroing after the barrier.
// Blocks [ntb, ntb+30): rel update (arrive at barrier immediately, then GEMV).
// Grid 421 <= 592 resident (smem 56.4KB, 64 regs -> 4 blocks/SM): barrier safe.
#define WRT_PAD 66
__global__ __launch_bounds__(256, 4) void node_transform(
    const float* __restrict__ nfeat_in0,
    const float* __restrict__ WS, const float* __restrict__ WO,
    const float* __restrict__ WI, const float* __restrict__ LR,
    const float* __restrict__ gamma, const float* __restrict__ beta,
    const float* __restrict__ WR, float* __restrict__ out_r,
    const float* __restrict__ LR_next,
    float* __restrict__ out_n,
    int rows, int layer, int ntb)
{
    extern __shared__ float smem[];
    const int tid = threadIdx.x;

    if (blockIdx.x >= ntb) {
        // ---------- rel-update blocks ----------
        if (tid == 0) atomicAdd(&g_barrier, 1u);   // unblock nt blocks promptly
        float* sWRT = smem;                        // [k][j], padded
        for (int i4 = tid; i4 < 1024; i4 += 256) {
            int j  = i4 >> 4;
            int k4 = (i4 & 15) * 4;
            float4 w = __ldg(reinterpret_cast<const float4*>(WR + j * D + k4));
            sWRT[(k4 + 0) * WRT_PAD + j] = w.x;
            sWRT[(k4 + 1) * WRT_PAD + j] = w.y;
            sWRT[(k4 + 2) * WRT_PAD + j] = w.z;
            sWRT[(k4 + 3) * WRT_PAD + j] = w.w;
        }
        __syncthreads();
        int g = (blockIdx.x - ntb) * 256 + tid;
        int t = g >> 5;
        int lane = g & 31;
        int j0 = lane * 2;
        if (t < NUM_REL) {
            float* dst = layer ? out_r : g_rext;   // layer 0 rewrites r_ext in place
            float a0 = 0.f, a1 = 0.f;
#pragma unroll 8
            for (int k = 0; k < D; k++) {
                float v = __ldg(g_rext + t * D + k);            // warp broadcast
                float2 w2 = *reinterpret_cast<const float2*>(sWRT + k * WRT_PAD + j0);
                a0 += v * w2.x;
                a1 += v * w2.y;
            }
            __syncwarp();   // whole warp done reading row t before in-place write
            dst[t * D + j0]     = a0;
            dst[t * D + j0 + 1] = a1;
        } else if (t == NUM_REL && layer == 0) {
            g_rext[NUM_REL * D + j0]     = __ldg(LR_next + j0);
            g_rext[NUM_REL * D + j0 + 1] = __ldg(LR_next + j0 + 1);
        }
        return;
    }

    // ---------- GEMM tile blocks ----------
    float* sW = smem;                    // [192][NT_WPAD]
    float* sX = smem + 192 * NT_WPAD;    // [NT_XK][NT_XPAD]

    const float* __restrict__ nf = layer ? g_nbuf : nfeat_in0;
    const int tr  = tid >> 4;
    const int tc  = tid & 15;
    const int row0 = blockIdx.x * NTB_ROWS;
    const float third = 1.0f / 3.0f;

    const float* wsrc[3] = {WS, WO, WI};
#pragma unroll
    for (int s = 0; s < 3; s++) {
        for (int i4 = tid; i4 < 1024; i4 += 256) {
            int c  = i4 >> 4;
            int k4 = (i4 & 15) * 4;
            float4 w = __ldg(reinterpret_cast<const float4*>(wsrc[s] + c * D + k4));
            float m0 = third, m1 = third, m2 = third, m3 = third;
            if (s == 0) {
                m0 *= __ldg(LR + k4);     m1 *= __ldg(LR + k4 + 1);
                m2 *= __ldg(LR + k4 + 2); m3 *= __ldg(LR + k4 + 3);
            }
            int kb = s * 64 + k4;
            sW[(kb + 0) * NT_WPAD + c] = w.x * m0;
            sW[(kb + 1) * NT_WPAD + c] = w.y * m1;
            sW[(kb + 2) * NT_WPAD + c] = w.z * m2;
            sW[(kb + 3) * NT_WPAD + c] = w.w * m3;
        }
    }

    unsigned long long acc2[4][4];
#pragma unroll
    for (int rp = 0; rp < 4; rp++)
#pragma unroll
        for (int c = 0; c < 4; c++) acc2[rp][c] = 0ULL;

    const float* xsrc[3] = {nf, g_SO, g_SI};
    const int xoff = tr * 8;
    const int woff = tc * 4;

#pragma unroll
    for (int s = 0; s < 3; s++) {
#pragma unroll
        for (int ch = 0; ch < 8; ch++) {
            __syncthreads();
            {
                int row = tid >> 1;
                int k4  = (tid & 1) * 4;
                int grow = row0 + row;
                float4 v = make_float4(0.f, 0.f, 0.f, 0.f);
                if (grow < rows)
                    v = __ldg(reinterpret_cast<const float4*>(
                            xsrc[s] + (size_t)grow * D + ch * NT_XK + k4));
                sX[(k4 + 0) * NT_XPAD + row] = v.x;
                sX[(k4 + 1) * NT_XPAD + row] = v.y;
                sX[(k4 + 2) * NT_XPAD + row] = v.z;
                sX[(k4 + 3) * NT_XPAD + row] = v.w;
            }
            __syncthreads();

            const float* wseg = sW + (s * 64 + ch * NT_XK) * NT_WPAD + woff;
#pragma unroll
            for (int k = 0; k < NT_XK; k++) {
                ulonglong2 xa = *reinterpret_cast<const ulonglong2*>(sX + k * NT_XPAD + xoff);
                ulonglong2 xb = *reinterpret_cast<const ulonglong2*>(sX + k * NT_XPAD + xoff + 4);
                float4 wv = *reinterpret_cast<const float4*>(wseg + k * NT_WPAD);

                unsigned long long wd0 = pack2(wv.x, wv.x);
                unsigned long long wd1 = pack2(wv.y, wv.y);
                unsigned long long wd2 = pack2(wv.z, wv.z);
                unsigned long long wd3 = pack2(wv.w, wv.w);

                fma2(acc2[0][0], xa.x, wd0); fma2(acc2[0][1], xa.x, wd1);
                fma2(acc2[0][2], xa.x, wd2); fma2(acc2[0][3], xa.x, wd3);
                fma2(acc2[1][0], xa.y, wd0); fma2(acc2[1][1], xa.y, wd1);
                fma2(acc2[1][2], xa.y, wd2); fma2(acc2[1][3], xa.y, wd3);
                fma2(acc2[2][0], xb.x, wd0); fma2(acc2[2][1], xb.x, wd1);
                fma2(acc2[2][2], xb.x, wd2); fma2(acc2[2][3], xb.x, wd3);
                fma2(acc2[3][0], xb.y, wd0); fma2(acc2[3][1], xb.y, wd1);
                fma2(acc2[3][2], xb.y, wd2); fma2(acc2[3][3], xb.y, wd3);
            }
        }
    }

    // ---- per-thread BN partial stats (acc2 stays live) ----
    float s_[4] = {0.f, 0.f, 0.f, 0.f};
    float q_[4] = {0.f, 0.f, 0.f, 0.f};
#pragma unroll
    for (int rp = 0; rp < 4; rp++) {
        float lo[4], hi[4];
#pragma unroll
        for (int c = 0; c < 4; c++) unpack2(acc2[rp][c], lo[c], hi[c]);
        int r0g = row0 + tr * 8 + rp * 2;
        if (r0g < rows) {
#pragma unroll
            for (int c = 0; c < 4; c++) { s_[c] += lo[c]; q_[c] += lo[c] * lo[c]; }
        }
        if (r0g + 1 < rows) {
#pragma unroll
            for (int c = 0; c < 4; c++) { s_[c] += hi[c]; q_[c] += hi[c] * hi[c]; }
        }
    }

    // ---- block reduce stats into g_sum/g_sumsq ----
    __syncthreads();
    float* redS = sW;
    float* redQ = sW + 1024;
#pragma unroll
    for (int c = 0; c < 4; c++) {
        redS[(woff + c) * 16 + tr] = s_[c];
        redQ[(woff + c) * 16 + tr] = q_[c];
    }
    __syncthreads();
    if (tid < D) {
        float ss = 0.f, qq = 0.f;
#pragma unroll
        for (int t = 0; t < 16; t++) {
            ss += redS[tid * 16 + t];
            qq += redQ[tid * 16 + t];
        }
        atomicAdd(&g_sum[tid],   ss);
        atomicAdd(&g_sumsq[tid], qq);
    }
    __syncthreads();

    // ---- grid barrier (all gridDim.x blocks arrive; only GEMM blocks spin) ----
    if (tid == 0) {
        __threadfence();
        atomicAdd(&g_barrier, 1u);
        while (atomicAdd(&g_barrier, 0u) < (unsigned)gridDim.x) { }
    }
    __syncthreads();

    // ---- compute BN scale/shift (fresh L2 reads) ----
    float* ssc = sW + 2048;
    float* ssh = sW + 2048 + D;
    if (tid < D) {
        float invN = 1.0f / (float)rows;
        float mean = __ldcg(&g_sum[tid]) * invN;
        float var  = fmaxf(__ldcg(&g_sumsq[tid]) * invN - mean * mean, 0.f);
        float rstd = rsqrtf(var + BN_EPS);
        float g = __ldg(gamma + tid);
        ssc[tid] = rstd * g;
        ssh[tid] = __ldg(beta + tid) - mean * rstd * g;
    }
    __syncthreads();

    // ---- apply BN + tanh to live accumulators, store directly ----
    float* dstp = layer ? out_n : g_nbuf;
    float4 sc = *reinterpret_cast<const float4*>(ssc + woff);
    float4 sh = *reinterpret_cast<const float4*>(ssh + woff);
#pragma unroll
    for (int rp = 0; rp < 4; rp++) {
        float lo[4], hi[4];
#pragma unroll
        for (int c = 0; c < 4; c++) unpack2(acc2[rp][c], lo[c], hi[c]);
        int r0g = row0 + tr * 8 + rp * 2;
        if (r0g < rows) {
            float4 y;
            y.x = tanhf(lo[0] * sc.x + sh.x);
            y.y = tanhf(lo[1] * sc.y + sh.y);
            y.z = tanhf(lo[2] * sc.z + sh.z);
            y.w = tanhf(lo[3] * sc.w + sh.w);
            *reinterpret_cast<float4*>(dstp + (size_t)r0g * D + woff) = y;
        }
        if (r0g + 1 < rows) {
            float4 y;
            y.x = tanhf(hi[0] * sc.x + sh.x);
            y.y = tanhf(hi[1] * sc.y + sh.y);
            y.z = tanhf(hi[2] * sc.z + sh.z);
            y.w = tanhf(hi[3] * sc.w + sh.w);
            *reinterpret_cast<float4*>(dstp + (size_t)(r0g + 1) * D + woff) = y;
        }
    }

    // ---- layer 0: zero SO/SI for next layer (all reads done past the barrier) ----
    if (layer == 0) {
        const int n4 = NUM_ENT * D / 4;
        float4 z = make_float4(0.f, 0.f, 0.f, 0.f);
        int stride = ntb * 256;
        for (int i = blockIdx.x * 256 + tid; i < n4; i += stride) {
            reinterpret_cast<float4*>(g_SO)[i] = z;
            reinterpret_cast<float4*>(g_SI)[i] = z;
        }
    }
}

// ---------------- launch ----------------
extern "C" void kernel_launch(void* const* d_in, const int* in_sizes, int n_in,
                              void* d_out, int out_size) {
    const float* n0   = (const float*)d_in[0];
    const float* r0   = (const float*)d_in[1];
    const float* norm = (const float*)d_in[2];
    const int*   src  = (const int*)d_in[3];
    const int*   dst  = (const int*)d_in[4];
    const int*   et   = (const int*)d_in[5];
    const int*   msk  = (const int*)d_in[6];
    const int E    = in_sizes[3];
    const int rows = in_sizes[0] / D;

    float* out   = (float*)d_out;
    float* out_n = out;
    float* out_r = out + (size_t)NUM_ENT * D;

    cudaFuncSetAttribute(node_transform,
                         cudaFuncAttributeMaxDynamicSharedMemorySize, NT_SMEM);

    const int ntb = (rows + NTB_ROWS - 1) / NTB_ROWS;   // 391

    init_kernel<<<512, 256>>>(r0, (const float*)d_in[11]);

    for (int l = 0; l < 2; l++) {
        const float* WO = (const float*)d_in[7  + 7 * l];
        const float* WI = (const float*)d_in[8  + 7 * l];
        const float* WS = (const float*)d_in[9  + 7 * l];
        const float* WR = (const float*)d_in[10 + 7 * l];
        const float* LR = (const float*)d_in[11 + 7 * l];
        const float* GA = (const float*)d_in[12 + 7 * l];
        const float* BE = (const float*)d_in[13 + 7 * l];
        const float* LRn = (const float*)d_in[11 + 7 * 1];

        {
            long long threads = ((long long)E + 3) / 4 * 16;
            int blocks = (int)((threads + 255) / 256);
            edge_scatter<<<blocks, 256>>>(n0, src, dst, et, msk, norm, E, l);
        }
        node_transform<<<ntb + REL_BLOCKS, 256, NT_SMEM>>>(
            n0, WS, WO, WI, LR, GA, BE, WR, out_r, LRn, out_n, rows, l, ntb);
    }
}